// round 1
// baseline (speedup 1.0000x reference)
#include <cuda_runtime.h>
#include <math.h>

#define Bb 8
#define Ss 256
#define Tt 32
#define Dd 512
#define NROWS 2048   // B*S
#define MROWS 256    // B*T

// Scratch (allocation-free rule: __device__ globals)
__device__ float g_H[NROWS * Dd];   // tanh(enc_flat @ W1 + b1)
__device__ float g_F[NROWS * Dd];   // tanh(z_flat   @ W3 + b3)
__device__ float g_A[MROWS * Dd];   // tanh(output   @ W2 + b2)
__device__ float g_C[MROWS * Dd];   // tanh(output   @ W4 + b4)

// ---------------------------------------------------------------------------
// Generic tiled fp32 GEMM: out[M,N] = tanh(A[M,K] @ W[K,N] + bias[N])
// ---------------------------------------------------------------------------
template<int BM, int BN, int BK, int TM, int TN>
__global__ void __launch_bounds__((BM/TM)*(BN/TN))
gemm_bias_tanh(const float* __restrict__ A, const float* __restrict__ W,
               const float* __restrict__ bias, float* __restrict__ out,
               int M, int N, int K)
{
    constexpr int THREADS = (BM/TM)*(BN/TN);
    __shared__ float As[BK][BM];
    __shared__ float Bs[BK][BN];

    const int tid = threadIdx.x;
    const int tx  = tid % (BN/TN);
    const int ty  = tid / (BN/TN);
    const int bm  = blockIdx.y * BM;
    const int bn  = blockIdx.x * BN;

    float acc[TM][TN];
    #pragma unroll
    for (int i = 0; i < TM; i++)
        #pragma unroll
        for (int j = 0; j < TN; j++) acc[i][j] = 0.f;

    for (int k0 = 0; k0 < K; k0 += BK) {
        #pragma unroll 2
        for (int idx = tid; idx < BM*BK; idx += THREADS) {
            int m = idx / BK, k = idx % BK;
            As[k][m] = A[(size_t)(bm + m) * K + k0 + k];
        }
        #pragma unroll 2
        for (int idx = tid; idx < BK*BN; idx += THREADS) {
            int k = idx / BN, n = idx % BN;
            Bs[k][n] = W[(size_t)(k0 + k) * N + bn + n];
        }
        __syncthreads();
        #pragma unroll
        for (int k = 0; k < BK; k++) {
            float ra[TM], rb[TN];
            #pragma unroll
            for (int i = 0; i < TM; i++) ra[i] = As[k][ty*TM + i];
            #pragma unroll
            for (int j = 0; j < TN; j++) rb[j] = Bs[k][tx*TN + j];
            #pragma unroll
            for (int i = 0; i < TM; i++)
                #pragma unroll
                for (int j = 0; j < TN; j++)
                    acc[i][j] = fmaf(ra[i], rb[j], acc[i][j]);
        }
        __syncthreads();
    }

    #pragma unroll
    for (int i = 0; i < TM; i++) {
        int m = bm + ty*TM + i;
        #pragma unroll
        for (int j = 0; j < TN; j++) {
            int n = bn + tx*TN + j;
            out[(size_t)m * N + n] = tanhf(acc[i][j] + bias[n]);
        }
    }
}

// ---------------------------------------------------------------------------
// Fused dual-attention:
//  gamma[b,s,t,d] = softmax_s( A[m,d]*H[n,d] + C[m,d]*F[n,d] ),  n=b*S+s, m=b*T+t
//  attn[b,t,s,d]  = gamma
//  contex[b,t,d]  = sum_s gamma * enc[n,d]
//  concat[b,t, 0:D ] = output,  concat[b,t, D:2D] = contex
// Block: (d-tile of 32, t-half of 16, b). 512 threads: d = tid&31, schunk = tid>>5.
// ---------------------------------------------------------------------------
__global__ void __launch_bounds__(512)
attn_kernel(const float* __restrict__ H, const float* __restrict__ F,
            const float* __restrict__ Amat, const float* __restrict__ Cmat,
            const float* __restrict__ enc, const float* __restrict__ outp,
            float* __restrict__ concat, float* __restrict__ attn)
{
    extern __shared__ float sm[];
    float* Hs   = sm;               // [256][32]
    float* Fs   = sm + 8192;        // [256][32]
    float* Es   = sm + 16384;       // [256][32]
    float* redA = sm + 24576;       // [16][32]
    float* redB = sm + 25088;       // [16][32]

    const int tid = threadIdx.x;
    const int d   = tid & 31;
    const int sc  = tid >> 5;        // 0..15, owns s in [sc*16, sc*16+16)
    const int d0  = blockIdx.x * 32;
    const int t0  = blockIdx.y * 16;
    const int b   = blockIdx.z;
    const size_t rowbase = (size_t)b * Ss;

    // Load H/F/enc column tiles (coalesced 128B per s-row)
    for (int idx = tid; idx < Ss * 32; idx += 512) {
        int s  = idx >> 5;
        int dl = idx & 31;
        size_t g = (rowbase + s) * Dd + d0 + dl;
        Hs[idx] = H[g];
        Fs[idx] = F[g];
        Es[idx] = enc[g];
    }
    __syncthreads();

    const int sb = sc * 16;

    for (int tt = 0; tt < 16; tt++) {
        const int m = b * Tt + t0 + tt;
        // fold log2(e) into the scalars so we can use exp2f (pure MUFU.EX2)
        const float a = Amat[(size_t)m * Dd + d0 + d] * 1.4426950408889634f;
        const float c = Cmat[(size_t)m * Dd + d0 + d] * 1.4426950408889634f;

        float l[16];
        float mx = -1e30f;
        #pragma unroll
        for (int k = 0; k < 16; k++) {
            int s = sb + k;
            l[k] = fmaf(a, Hs[s*32 + d], c * Fs[s*32 + d]);
            mx = fmaxf(mx, l[k]);
        }
        redA[sc*32 + d] = mx;
        __syncthreads();
        mx = redA[d];
        #pragma unroll
        for (int k = 1; k < 16; k++) mx = fmaxf(mx, redA[k*32 + d]);

        float sum = 0.f;
        #pragma unroll
        for (int k = 0; k < 16; k++) {
            float e = exp2f(l[k] - mx);
            l[k] = e;
            sum += e;
        }
        redB[sc*32 + d] = sum;
        __syncthreads();
        sum = redB[d];
        #pragma unroll
        for (int k = 1; k < 16; k++) sum += redB[k*32 + d];
        const float inv = 1.0f / sum;

        float ctx = 0.f;
        float* ab = attn + ((size_t)m * Ss + sb) * Dd + d0 + d;
        #pragma unroll
        for (int k = 0; k < 16; k++) {
            float g = l[k] * inv;
            ab[(size_t)k * Dd] = g;                       // warp: 32 consecutive d -> 128B store
            ctx = fmaf(g, Es[(sb + k)*32 + d], ctx);
        }
        redA[sc*32 + d] = ctx;   // redA reads (max) all completed before redB sync
        __syncthreads();
        if (sc == 0) {
            float cx = 0.f;
            #pragma unroll
            for (int k = 0; k < 16; k++) cx += redA[k*32 + d];
            concat[(size_t)m * (2*Dd) + Dd + d0 + d] = cx;
        } else if (sc == 1) {
            concat[(size_t)m * (2*Dd) + d0 + d] = outp[(size_t)m * Dd + d0 + d];
        }
        __syncthreads();
    }
}

// ---------------------------------------------------------------------------
extern "C" void kernel_launch(void* const* d_in, const int* in_sizes, int n_in,
                              void* d_out, int out_size)
{
    const float* output = (const float*)d_in[0];   // [8,32,512]
    const float* enc    = (const float*)d_in[1];   // [256,8,512] -> flat [2048,512]
    const float* z      = (const float*)d_in[2];   // [8,256,128] -> flat [2048,128]
    const float* W1 = (const float*)d_in[3];
    const float* b1 = (const float*)d_in[4];
    const float* W2 = (const float*)d_in[5];
    const float* b2 = (const float*)d_in[6];
    const float* W3 = (const float*)d_in[7];
    const float* b3 = (const float*)d_in[8];
    const float* W4 = (const float*)d_in[9];
    const float* b4 = (const float*)d_in[10];

    float* concat = (float*)d_out;                       // [8,32,1024] = 262144 floats
    float* attn   = concat + (size_t)Bb * Tt * 2 * Dd;   // [8,32,256,512]

    float *pH, *pF, *pA, *pC;
    cudaGetSymbolAddress((void**)&pH, g_H);
    cudaGetSymbolAddress((void**)&pF, g_F);
    cudaGetSymbolAddress((void**)&pA, g_A);
    cudaGetSymbolAddress((void**)&pC, g_C);

    // H = tanh(enc_flat @ W1 + b1)      [2048,512] x [512,512]
    gemm_bias_tanh<64,64,16,4,4><<<dim3(Dd/64, NROWS/64), 256>>>(enc, W1, b1, pH, NROWS, Dd, 512);
    // F = tanh(z_flat @ W3 + b3)        [2048,128] x [128,512]
    gemm_bias_tanh<64,64,16,4,4><<<dim3(Dd/64, NROWS/64), 256>>>(z, W3, b3, pF, NROWS, Dd, 128);
    // A = tanh(output @ W2 + b2)        [256,512] x [512,512]
    gemm_bias_tanh<32,64,16,2,4><<<dim3(Dd/64, MROWS/32), 256>>>(output, W2, b2, pA, MROWS, Dd, 512);
    // C = tanh(output @ W4 + b4)
    gemm_bias_tanh<32,64,16,2,4><<<dim3(Dd/64, MROWS/32), 256>>>(output, W4, b4, pC, MROWS, Dd, 512);

    // Fused softmax + attn + contex + concat
    const int smem_bytes = (3*8192 + 2*512) * (int)sizeof(float);  // 102400
    cudaFuncSetAttribute(attn_kernel, cudaFuncAttributeMaxDynamicSharedMemorySize, smem_bytes);
    attn_kernel<<<dim3(16, 2, Bb), 512, smem_bytes>>>(pH, pF, pA, pC, enc, output, concat, attn);
}

// round 2
// speedup vs baseline: 2.0788x; 2.0788x over previous
#include <cuda_runtime.h>
#include <math.h>

#define Bb 8
#define Ss 256
#define Tt 32
#define Dd 512
#define NROWS 2048   // B*S
#define MROWS 256    // B*T

// Scratch (allocation-free rule: __device__ globals)
__device__ float g_H[NROWS * Dd];   // tanh(enc_flat @ W1 + b1)
__device__ float g_F[NROWS * Dd];   // tanh(z_flat   @ W3 + b3)
__device__ float g_A[MROWS * Dd];   // tanh(output   @ W2 + b2)
__device__ float g_C[MROWS * Dd];   // tanh(output   @ W4 + b4)

// ---------------------------------------------------------------------------
// packed f32x2 helpers (sm_100+: one FFMA2 = 2 fp32 FMAs)
// ---------------------------------------------------------------------------
typedef unsigned long long ull;

__device__ __forceinline__ ull pack2(float x, float y) {
    ull r;
    asm("mov.b64 %0, {%1, %2};" : "=l"(r) : "f"(x), "f"(y));
    return r;
}
__device__ __forceinline__ void unpack2(ull v, float& x, float& y) {
    asm("mov.b64 {%0, %1}, %2;" : "=f"(x), "=f"(y) : "l"(v));
}
__device__ __forceinline__ void ffma2(ull& d, ull a, ull b) {
    asm("fma.rn.f32x2 %0, %1, %2, %0;" : "+l"(d) : "l"(a), "l"(b));
}

// ---------------------------------------------------------------------------
// Mega-GEMM: all four  out = tanh(src @ W + bias)  problems in ONE launch.
//   BM=128, BN=64, BK=16, 256 threads, TM=8, TN=4 (as f32x2 pairs).
// Block decode (N=512 for all, so 8 n-blocks):
//   [0,128)   : H = tanh(enc  @ W1 + b1)   M=2048 K=512
//   [128,256) : F = tanh(z    @ W3 + b3)   M=2048 K=128
//   [256,272) : A = tanh(outp @ W2 + b2)   M=256  K=512
//   [272,288) : C = tanh(outp @ W4 + b4)   M=256  K=512
// ---------------------------------------------------------------------------
__global__ void __launch_bounds__(256, 3)
megagemm(const float* __restrict__ enc, const float* __restrict__ z,
         const float* __restrict__ outp,
         const float* __restrict__ W1, const float* __restrict__ b1,
         const float* __restrict__ W2, const float* __restrict__ b2,
         const float* __restrict__ W3, const float* __restrict__ b3,
         const float* __restrict__ W4, const float* __restrict__ b4,
         float* __restrict__ H, float* __restrict__ F,
         float* __restrict__ A, float* __restrict__ C)
{
    __shared__ float As[16][128];
    __shared__ float Bs[16][64];

    int bid = blockIdx.x;
    const float *src, *W, *bias;
    float* dst;
    int K;
    if (bid < 128)      { src = enc;  W = W1; bias = b1; dst = H; K = 512; }
    else if (bid < 256) { src = z;    W = W3; bias = b3; dst = F; K = 128; bid -= 128; }
    else if (bid < 272) { src = outp; W = W2; bias = b2; dst = A; K = 512; bid -= 256; }
    else                { src = outp; W = W4; bias = b4; dst = C; K = 512; bid -= 272; }
    const int nb = bid & 7;          // n block (always 8 of them: 512/64)
    const int mb = bid >> 3;         // m block

    const int tid = threadIdx.x;
    const int tx  = tid & 15;        // n subtile
    const int ty  = tid >> 4;        // m subtile

    ull acc[8][2];
    #pragma unroll
    for (int i = 0; i < 8; i++) { acc[i][0] = 0ull; acc[i][1] = 0ull; }

    for (int k0 = 0; k0 < K; k0 += 16) {
        // A tile: 128 rows x 16 k.  512 float4s, 2 per thread.
        #pragma unroll
        for (int q = 0; q < 2; q++) {
            int f  = tid * 2 + q;
            int m  = f >> 2;
            int kq = (f & 3) << 2;
            float4 v = *(const float4*)&src[(size_t)(mb * 128 + m) * K + k0 + kq];
            As[kq + 0][m] = v.x;
            As[kq + 1][m] = v.y;
            As[kq + 2][m] = v.z;
            As[kq + 3][m] = v.w;
        }
        // B tile: 16 k x 64 n.  256 float4s, 1 per thread.
        {
            int kk = tid >> 4;
            int n4 = (tid & 15) << 2;
            *(float4*)&Bs[kk][n4] =
                *(const float4*)&W[(size_t)(k0 + kk) * 512 + nb * 64 + n4];
        }
        __syncthreads();

        #pragma unroll
        for (int k = 0; k < 16; k++) {
            float4 a0 = *(const float4*)&As[k][ty * 8];
            float4 a1 = *(const float4*)&As[k][ty * 8 + 4];
            float4 bv = *(const float4*)&Bs[k][tx * 4];
            ull b0 = pack2(bv.x, bv.y);
            ull b1p = pack2(bv.z, bv.w);
            float ar[8] = {a0.x, a0.y, a0.z, a0.w, a1.x, a1.y, a1.z, a1.w};
            #pragma unroll
            for (int i = 0; i < 8; i++) {
                ull ap = pack2(ar[i], ar[i]);
                ffma2(acc[i][0], ap, b0);
                ffma2(acc[i][1], ap, b1p);
            }
        }
        __syncthreads();
    }

    float4 bv = *(const float4*)&bias[nb * 64 + tx * 4];
    #pragma unroll
    for (int i = 0; i < 8; i++) {
        float x0, x1, x2, x3;
        unpack2(acc[i][0], x0, x1);
        unpack2(acc[i][1], x2, x3);
        float4 o;
        o.x = tanhf(x0 + bv.x);
        o.y = tanhf(x1 + bv.y);
        o.z = tanhf(x2 + bv.z);
        o.w = tanhf(x3 + bv.w);
        *(float4*)&dst[(size_t)(mb * 128 + ty * 8 + i) * 512 + nb * 64 + tx * 4] = o;
    }
}

// ---------------------------------------------------------------------------
// Fused dual-attention (unchanged from R1 — DRAM-bound):
//  gamma[b,s,t,d] = softmax_s( A[m,d]*H[n,d] + C[m,d]*F[n,d] ),  n=b*S+s, m=b*T+t
//  attn[b,t,s,d]  = gamma
//  contex[b,t,d]  = sum_s gamma * enc[n,d]
//  concat[b,t, 0:D ] = output,  concat[b,t, D:2D] = contex
// ---------------------------------------------------------------------------
__global__ void __launch_bounds__(512)
attn_kernel(const float* __restrict__ H, const float* __restrict__ F,
            const float* __restrict__ Amat, const float* __restrict__ Cmat,
            const float* __restrict__ enc, const float* __restrict__ outp,
            float* __restrict__ concat, float* __restrict__ attn)
{
    extern __shared__ float sm[];
    float* Hs   = sm;               // [256][32]
    float* Fs   = sm + 8192;        // [256][32]
    float* Es   = sm + 16384;       // [256][32]
    float* redA = sm + 24576;       // [16][32]
    float* redB = sm + 25088;       // [16][32]

    const int tid = threadIdx.x;
    const int d   = tid & 31;
    const int sc  = tid >> 5;        // 0..15, owns s in [sc*16, sc*16+16)
    const int d0  = blockIdx.x * 32;
    const int t0  = blockIdx.y * 16;
    const int b   = blockIdx.z;
    const size_t rowbase = (size_t)b * Ss;

    for (int idx = tid; idx < Ss * 32; idx += 512) {
        int s  = idx >> 5;
        int dl = idx & 31;
        size_t g = (rowbase + s) * Dd + d0 + dl;
        Hs[idx] = H[g];
        Fs[idx] = F[g];
        Es[idx] = enc[g];
    }
    __syncthreads();

    const int sb = sc * 16;

    for (int tt = 0; tt < 16; tt++) {
        const int m = b * Tt + t0 + tt;
        const float a = Amat[(size_t)m * Dd + d0 + d] * 1.4426950408889634f;
        const float c = Cmat[(size_t)m * Dd + d0 + d] * 1.4426950408889634f;

        float l[16];
        float mx = -1e30f;
        #pragma unroll
        for (int k = 0; k < 16; k++) {
            int s = sb + k;
            l[k] = fmaf(a, Hs[s*32 + d], c * Fs[s*32 + d]);
            mx = fmaxf(mx, l[k]);
        }
        redA[sc*32 + d] = mx;
        __syncthreads();
        mx = redA[d];
        #pragma unroll
        for (int k = 1; k < 16; k++) mx = fmaxf(mx, redA[k*32 + d]);

        float sum = 0.f;
        #pragma unroll
        for (int k = 0; k < 16; k++) {
            float e = exp2f(l[k] - mx);
            l[k] = e;
            sum += e;
        }
        redB[sc*32 + d] = sum;
        __syncthreads();
        sum = redB[d];
        #pragma unroll
        for (int k = 1; k < 16; k++) sum += redB[k*32 + d];
        const float inv = 1.0f / sum;

        float ctx = 0.f;
        float* ab = attn + ((size_t)m * Ss + sb) * Dd + d0 + d;
        #pragma unroll
        for (int k = 0; k < 16; k++) {
            float g = l[k] * inv;
            ab[(size_t)k * Dd] = g;
            ctx = fmaf(g, Es[(sb + k)*32 + d], ctx);
        }
        redA[sc*32 + d] = ctx;
        __syncthreads();
        if (sc == 0) {
            float cx = 0.f;
            #pragma unroll
            for (int k = 0; k < 16; k++) cx += redA[k*32 + d];
            concat[(size_t)m * (2*Dd) + Dd + d0 + d] = cx;
        } else if (sc == 1) {
            concat[(size_t)m * (2*Dd) + d0 + d] = outp[(size_t)m * Dd + d0 + d];
        }
        __syncthreads();
    }
}

// ---------------------------------------------------------------------------
extern "C" void kernel_launch(void* const* d_in, const int* in_sizes, int n_in,
                              void* d_out, int out_size)
{
    const float* output = (const float*)d_in[0];   // [8,32,512]
    const float* enc    = (const float*)d_in[1];   // [256,8,512] -> flat [2048,512]
    const float* z      = (const float*)d_in[2];   // [8,256,128] -> flat [2048,128]
    const float* W1 = (const float*)d_in[3];
    const float* b1 = (const float*)d_in[4];
    const float* W2 = (const float*)d_in[5];
    const float* b2 = (const float*)d_in[6];
    const float* W3 = (const float*)d_in[7];
    const float* b3 = (const float*)d_in[8];
    const float* W4 = (const float*)d_in[9];
    const float* b4 = (const float*)d_in[10];

    float* concat = (float*)d_out;                       // [8,32,1024]
    float* attn   = concat + (size_t)Bb * Tt * 2 * Dd;   // [8,32,256,512]

    float *pH, *pF, *pA, *pC;
    cudaGetSymbolAddress((void**)&pH, g_H);
    cudaGetSymbolAddress((void**)&pF, g_F);
    cudaGetSymbolAddress((void**)&pA, g_A);
    cudaGetSymbolAddress((void**)&pC, g_C);

    // All four GEMM+tanh problems in one launch (288 blocks).
    megagemm<<<288, 256>>>(enc, z, output,
                           W1, b1, W2, b2, W3, b3, W4, b4,
                           pH, pF, pA, pC);

    // Fused softmax + attn + contex + concat
    const int smem_bytes = (3*8192 + 2*512) * (int)sizeof(float);  // 102400
    cudaFuncSetAttribute(attn_kernel, cudaFuncAttributeMaxDynamicSharedMemorySize, smem_bytes);
    attn_kernel<<<dim3(16, 2, Bb), 512, smem_bytes>>>(pH, pF, pA, pC, enc, output, concat, attn);
}

// round 3
// speedup vs baseline: 2.4823x; 1.1941x over previous
#include <cuda_runtime.h>
#include <math.h>

#define Bb 8
#define Ss 256
#define Tt 32
#define Dd 512
#define NROWS 2048   // B*S
#define MROWS 256    // B*T

// Scratch (allocation-free rule: __device__ globals)
__device__ float g_H[NROWS * Dd];
__device__ float g_F[NROWS * Dd];
__device__ float g_A[MROWS * Dd];
__device__ float g_C[MROWS * Dd];

typedef unsigned long long ull;

__device__ __forceinline__ ull pack2(float x, float y) {
    ull r;
    asm("mov.b64 %0, {%1, %2};" : "=l"(r) : "f"(x), "f"(y));
    return r;
}
__device__ __forceinline__ void unpack2(ull v, float& x, float& y) {
    asm("mov.b64 {%0, %1}, %2;" : "=f"(x), "=f"(y) : "l"(v));
}
__device__ __forceinline__ void ffma2(ull& d, ull a, ull b) {
    asm("fma.rn.f32x2 %0, %1, %2, %0;" : "+l"(d) : "l"(a), "l"(b));
}

// ---------------------------------------------------------------------------
// Mega-GEMM: all four  out = tanh(src @ W + bias)  in ONE launch.
// BM=128, BN=128, BK=16, 256 threads, per-thread 8x8 via f32x2 pairs along M.
// Blocks: [0,64) H (K=512) | [64,128) F (K=128) | [128,136) A | [136,144) C
// ---------------------------------------------------------------------------
__global__ void __launch_bounds__(256)
megagemm(const float* __restrict__ enc, const float* __restrict__ z,
         const float* __restrict__ outp,
         const float* __restrict__ W1, const float* __restrict__ b1,
         const float* __restrict__ W2, const float* __restrict__ b2,
         const float* __restrict__ W3, const float* __restrict__ b3,
         const float* __restrict__ W4, const float* __restrict__ b4,
         float* __restrict__ H, float* __restrict__ F,
         float* __restrict__ A, float* __restrict__ C)
{
    __shared__ float As[16][128];
    __shared__ float Bs[16][128];

    int bid = blockIdx.x;
    const float *src, *W, *bias;
    float* dst;
    int K;
    if (bid < 64)       { src = enc;  W = W1; bias = b1; dst = H; K = 512; }
    else if (bid < 128) { src = z;    W = W3; bias = b3; dst = F; K = 128; bid -= 64; }
    else if (bid < 136) { src = outp; W = W2; bias = b2; dst = A; K = 512; bid -= 128; }
    else                { src = outp; W = W4; bias = b4; dst = C; K = 512; bid -= 136; }
    const int nb = bid & 3;    // 512/128 = 4 n-blocks
    const int mb = bid >> 2;

    const int tid = threadIdx.x;
    const int tx  = tid & 15;
    const int ty  = tid >> 4;

    ull acc[4][8];
    #pragma unroll
    for (int i = 0; i < 4; i++)
        #pragma unroll
        for (int j = 0; j < 8; j++) acc[i][j] = 0ull;

    for (int k0 = 0; k0 < K; k0 += 16) {
        // Stage A tile: 128 m x 16 k  (512 float4, 2/thread), transposed to [k][m]
        #pragma unroll
        for (int q = 0; q < 2; q++) {
            int f  = tid * 2 + q;
            int m  = f >> 2;
            int kq = (f & 3) << 2;
            float4 v = *(const float4*)&src[(size_t)(mb * 128 + m) * K + k0 + kq];
            As[kq + 0][m] = v.x;
            As[kq + 1][m] = v.y;
            As[kq + 2][m] = v.z;
            As[kq + 3][m] = v.w;
        }
        // Stage B tile: 16 k x 128 n  (512 float4, 2/thread)
        #pragma unroll
        for (int q = 0; q < 2; q++) {
            int f  = tid * 2 + q;
            int kk = f >> 5;
            int n4 = (f & 31) << 2;
            *(float4*)&Bs[kk][n4] =
                *(const float4*)&W[(size_t)(k0 + kk) * 512 + nb * 128 + n4];
        }
        __syncthreads();

        #pragma unroll
        for (int k = 0; k < 16; k++) {
            // A: 8 consecutive m as 4 natural f32x2 pairs (broadcast across tx)
            const ull* ap = (const ull*)&As[k][ty * 8];
            ull a0 = ap[0], a1 = ap[1], a2 = ap[2], a3 = ap[3];
            // B: n = nb*128 + {tx*4+0..3, 64+tx*4+0..3}  (conflict-free stride)
            float4 p0 = *(const float4*)&Bs[k][tx * 4];
            float4 p1 = *(const float4*)&Bs[k][64 + tx * 4];
            ull bd[8];
            bd[0] = pack2(p0.x, p0.x); bd[1] = pack2(p0.y, p0.y);
            bd[2] = pack2(p0.z, p0.z); bd[3] = pack2(p0.w, p0.w);
            bd[4] = pack2(p1.x, p1.x); bd[5] = pack2(p1.y, p1.y);
            bd[6] = pack2(p1.z, p1.z); bd[7] = pack2(p1.w, p1.w);
            #pragma unroll
            for (int j = 0; j < 8; j++) {
                ffma2(acc[0][j], a0, bd[j]);
                ffma2(acc[1][j], a1, bd[j]);
                ffma2(acc[2][j], a2, bd[j]);
                ffma2(acc[3][j], a3, bd[j]);
            }
        }
        __syncthreads();
    }

    // Epilogue: bias + tanh + store (two float4 spans per row)
    float4 bv0 = *(const float4*)&bias[nb * 128 + tx * 4];
    float4 bv1 = *(const float4*)&bias[nb * 128 + 64 + tx * 4];
    #pragma unroll
    for (int i = 0; i < 4; i++) {
        int m0 = mb * 128 + ty * 8 + 2 * i;
        float lo[8], hi[8];
        #pragma unroll
        for (int j = 0; j < 8; j++) unpack2(acc[i][j], lo[j], hi[j]);

        float4 o;
        o.x = tanhf(lo[0] + bv0.x); o.y = tanhf(lo[1] + bv0.y);
        o.z = tanhf(lo[2] + bv0.z); o.w = tanhf(lo[3] + bv0.w);
        *(float4*)&dst[(size_t)m0 * 512 + nb * 128 + tx * 4] = o;
        o.x = tanhf(lo[4] + bv1.x); o.y = tanhf(lo[5] + bv1.y);
        o.z = tanhf(lo[6] + bv1.z); o.w = tanhf(lo[7] + bv1.w);
        *(float4*)&dst[(size_t)m0 * 512 + nb * 128 + 64 + tx * 4] = o;

        o.x = tanhf(hi[0] + bv0.x); o.y = tanhf(hi[1] + bv0.y);
        o.z = tanhf(hi[2] + bv0.z); o.w = tanhf(hi[3] + bv0.w);
        *(float4*)&dst[(size_t)(m0 + 1) * 512 + nb * 128 + tx * 4] = o;
        o.x = tanhf(hi[4] + bv1.x); o.y = tanhf(hi[5] + bv1.y);
        o.z = tanhf(hi[6] + bv1.z); o.w = tanhf(hi[7] + bv1.w);
        *(float4*)&dst[(size_t)(m0 + 1) * 512 + nb * 128 + 64 + tx * 4] = o;
    }
}

// ---------------------------------------------------------------------------
// Barrier-free dual attention.
// gamma[b,s,t,d] = softmax_s( A[m,d]*H[n,d] + C[m,d]*F[n,d] ), n=b*S+s, m=b*T+t.
// No max subtraction needed: all factors are tanh outputs -> |logit| <= ~2.9
// in log2 domain, exp2 range [0.13, 7.5] -> numerically safe, result identical.
// Block = (d-tile of 32, b). 256 threads: thread = (t, d-quad), owns FULL s
// range -> softmax sum / normalize / context are thread-local. One barrier.
// ---------------------------------------------------------------------------
__global__ void __launch_bounds__(256)
attn_kernel(const float* __restrict__ H, const float* __restrict__ F,
            const float* __restrict__ Amat, const float* __restrict__ Cmat,
            const float* __restrict__ enc, const float* __restrict__ outp,
            float* __restrict__ concat, float* __restrict__ attn)
{
    extern __shared__ float sm[];
    float* Hs = sm;            // [256][32]
    float* Fs = sm + 8192;     // [256][32]
    float* Es = sm + 16384;    // [256][32]

    const int tid = threadIdx.x;
    const int dq  = (tid & 7) * 4;   // d-quad within 32-wide tile
    const int t   = tid >> 3;        // 0..31
    const int d0  = blockIdx.x * 32;
    const int b   = blockIdx.y;

    // Load tiles (float4, fully coalesced)
    for (int idx = tid; idx < 2048; idx += 256) {
        int s  = idx >> 3;
        int dl = (idx & 7) << 2;
        size_t g = ((size_t)(b * Ss + s)) * Dd + d0 + dl;
        *(float4*)&Hs[s * 32 + dl] = *(const float4*)&H[g];
        *(float4*)&Fs[s * 32 + dl] = *(const float4*)&F[g];
        *(float4*)&Es[s * 32 + dl] = *(const float4*)&enc[g];
    }
    __syncthreads();

    const int m = b * Tt + t;
    const float L2E = 1.4426950408889634f;
    float4 a4 = *(const float4*)&Amat[(size_t)m * Dd + d0 + dq];
    float4 c4 = *(const float4*)&Cmat[(size_t)m * Dd + d0 + dq];
    a4.x *= L2E; a4.y *= L2E; a4.z *= L2E; a4.w *= L2E;
    c4.x *= L2E; c4.y *= L2E; c4.z *= L2E; c4.w *= L2E;

    // Pass 1: softmax denominators (thread-local, no max needed)
    float sx = 0.f, sy = 0.f, sz = 0.f, sw = 0.f;
    #pragma unroll 4
    for (int s = 0; s < Ss; s++) {
        float4 h = *(const float4*)&Hs[s * 32 + dq];
        float4 f = *(const float4*)&Fs[s * 32 + dq];
        sx += exp2f(fmaf(a4.x, h.x, c4.x * f.x));
        sy += exp2f(fmaf(a4.y, h.y, c4.y * f.y));
        sz += exp2f(fmaf(a4.z, h.z, c4.z * f.z));
        sw += exp2f(fmaf(a4.w, h.w, c4.w * f.w));
    }
    const float ix = 1.f / sx, iy = 1.f / sy, iz = 1.f / sz, iw = 1.f / sw;

    // Pass 2: write gamma (= attn) and accumulate context
    float cx = 0.f, cy = 0.f, cz = 0.f, cw = 0.f;
    float* ab = attn + (size_t)m * Ss * Dd + d0 + dq;
    #pragma unroll 2
    for (int s = 0; s < Ss; s++) {
        float4 h = *(const float4*)&Hs[s * 32 + dq];
        float4 f = *(const float4*)&Fs[s * 32 + dq];
        float4 e = *(const float4*)&Es[s * 32 + dq];
        float4 g;
        g.x = exp2f(fmaf(a4.x, h.x, c4.x * f.x)) * ix;
        g.y = exp2f(fmaf(a4.y, h.y, c4.y * f.y)) * iy;
        g.z = exp2f(fmaf(a4.z, h.z, c4.z * f.z)) * iz;
        g.w = exp2f(fmaf(a4.w, h.w, c4.w * f.w)) * iw;
        *(float4*)&ab[(size_t)s * Dd] = g;
        cx = fmaf(g.x, e.x, cx);
        cy = fmaf(g.y, e.y, cy);
        cz = fmaf(g.z, e.z, cz);
        cw = fmaf(g.w, e.w, cw);
    }

    // concat: [output | contex]
    float4 ct; ct.x = cx; ct.y = cy; ct.z = cz; ct.w = cw;
    *(float4*)&concat[(size_t)m * (2 * Dd) + Dd + d0 + dq] = ct;
    *(float4*)&concat[(size_t)m * (2 * Dd) + d0 + dq] =
        *(const float4*)&outp[(size_t)m * Dd + d0 + dq];
}

// ---------------------------------------------------------------------------
extern "C" void kernel_launch(void* const* d_in, const int* in_sizes, int n_in,
                              void* d_out, int out_size)
{
    const float* output = (const float*)d_in[0];   // [8,32,512]
    const float* enc    = (const float*)d_in[1];   // [256,8,512] flat [2048,512]
    const float* z      = (const float*)d_in[2];   // [8,256,128] flat [2048,128]
    const float* W1 = (const float*)d_in[3];
    const float* b1 = (const float*)d_in[4];
    const float* W2 = (const float*)d_in[5];
    const float* b2 = (const float*)d_in[6];
    const float* W3 = (const float*)d_in[7];
    const float* b3 = (const float*)d_in[8];
    const float* W4 = (const float*)d_in[9];
    const float* b4 = (const float*)d_in[10];

    float* concat = (float*)d_out;                       // [8,32,1024]
    float* attn   = concat + (size_t)Bb * Tt * 2 * Dd;   // [8,32,256,512]

    float *pH, *pF, *pA, *pC;
    cudaGetSymbolAddress((void**)&pH, g_H);
    cudaGetSymbolAddress((void**)&pF, g_F);
    cudaGetSymbolAddress((void**)&pA, g_A);
    cudaGetSymbolAddress((void**)&pC, g_C);

    megagemm<<<144, 256>>>(enc, z, output,
                           W1, b1, W2, b2, W3, b3, W4, b4,
                           pH, pF, pA, pC);

    const int smem_bytes = 3 * 8192 * (int)sizeof(float);  // 98304
    cudaFuncSetAttribute(attn_kernel, cudaFuncAttributeMaxDynamicSharedMemorySize, smem_bytes);
    attn_kernel<<<dim3(16, Bb), 256, smem_bytes>>>(pH, pF, pA, pC, enc, output, concat, attn);
}

// round 5
// speedup vs baseline: 3.6814x; 1.4831x over previous
#include <cuda_runtime.h>
#include <cuda_bf16.h>
#include <math.h>
#include <stdint.h>

#define Bb 8
#define Ss 256
#define Tt 32
#define Dd 512
#define NROWS 2048   // B*S
#define MROWS 256    // B*T

// Scratch (allocation-free rule: __device__ globals)
__device__ float g_H[NROWS * Dd];
__device__ float g_F[NROWS * Dd];
__device__ float g_A[MROWS * Dd];
__device__ float g_C[MROWS * Dd];

// ---------------------------------------------------------------------------
// Warp-MMA helpers (baseline PTX, compiles for plain sm_103)
// ---------------------------------------------------------------------------
__device__ __forceinline__ uint32_t smem_to_u32(const void* p) {
    uint32_t a;
    asm("{ .reg .u64 t; cvta.to.shared.u64 t, %1; cvt.u32.u64 %0, t; }"
        : "=r"(a) : "l"(p));
    return a;
}
__device__ __forceinline__ void ldsm_x4(uint32_t* r, uint32_t addr) {
    asm volatile("ldmatrix.sync.aligned.m8n8.x4.shared.b16 {%0,%1,%2,%3}, [%4];"
        : "=r"(r[0]), "=r"(r[1]), "=r"(r[2]), "=r"(r[3]) : "r"(addr));
}
__device__ __forceinline__ void ldsm_x4_t(uint32_t* r, uint32_t addr) {
    asm volatile("ldmatrix.sync.aligned.m8n8.x4.trans.shared.b16 {%0,%1,%2,%3}, [%4];"
        : "=r"(r[0]), "=r"(r[1]), "=r"(r[2]), "=r"(r[3]) : "r"(addr));
}
__device__ __forceinline__ void mma_bf16(float* d, const uint32_t* a, const uint32_t* b) {
    asm volatile("mma.sync.aligned.m16n8k16.row.col.f32.bf16.bf16.f32 "
        "{%0,%1,%2,%3}, {%4,%5,%6,%7}, {%8,%9}, {%0,%1,%2,%3};"
        : "+f"(d[0]), "+f"(d[1]), "+f"(d[2]), "+f"(d[3])
        : "r"(a[0]), "r"(a[1]), "r"(a[2]), "r"(a[3]), "r"(b[0]), "r"(b[1]));
}
__device__ __forceinline__ uint32_t pb2(__nv_bfloat16 a, __nv_bfloat16 b) {
    __nv_bfloat162 t; t.x = a; t.y = b;
    return *(uint32_t*)&t;
}

// ---------------------------------------------------------------------------
// Mega-GEMM via mma.sync bf16 with hi/lo split-precision (3 MMAs / term).
//   out = tanh(src @ W + bias),  fp32 in/out, exact to ~2^-17 per product.
// CTA: 128m x 128n, BK=32 fp32-k per iter, 8 warps as 4m x 2n (warp 32x64).
// smem: Ahi/Alo [128][40] bf16 (pad->ldmatrix conflict-free),
//       Bhi/Blo [32][136] bf16 (k-major rows, same layout as gmem W).
// Blocks: [0,64) H (K=512) | [64,128) F (K=128) | [128,136) A | [136,144) C
// ---------------------------------------------------------------------------
__global__ void __launch_bounds__(256, 1)
megagemm_mma(const float* __restrict__ enc, const float* __restrict__ z,
             const float* __restrict__ outp,
             const float* __restrict__ W1, const float* __restrict__ b1,
             const float* __restrict__ W2, const float* __restrict__ b2,
             const float* __restrict__ W3, const float* __restrict__ b3,
             const float* __restrict__ W4, const float* __restrict__ b4,
             float* __restrict__ H, float* __restrict__ F,
             float* __restrict__ A, float* __restrict__ C)
{
    __shared__ __nv_bfloat16 Ahi[128 * 40];
    __shared__ __nv_bfloat16 Alo[128 * 40];
    __shared__ __nv_bfloat16 Bhi[32 * 136];
    __shared__ __nv_bfloat16 Blo[32 * 136];

    int bid = blockIdx.x;
    const float *src, *W, *bias;
    float* dst;
    int K;
    if (bid < 64)       { src = enc;  W = W1; bias = b1; dst = H; K = 512; }
    else if (bid < 128) { src = z;    W = W3; bias = b3; dst = F; K = 128; bid -= 64; }
    else if (bid < 136) { src = outp; W = W2; bias = b2; dst = A; K = 512; bid -= 128; }
    else                { src = outp; W = W4; bias = b4; dst = C; K = 512; bid -= 136; }
    const int nb = bid & 3;
    const int mb = bid >> 2;
    const int m0 = mb * 128, n0 = nb * 128;

    const int tid  = threadIdx.x;
    const int lane = tid & 31;
    const int wid  = tid >> 5;
    const int wm   = wid & 3;    // m quarter (32 rows)
    const int wn   = wid >> 2;   // n half (64 cols)

    const uint32_t aHiB = smem_to_u32(Ahi);
    const uint32_t aLoB = smem_to_u32(Alo);
    const uint32_t bHiB = smem_to_u32(Bhi);
    const uint32_t bLoB = smem_to_u32(Blo);

    float acc[2][8][4];
    #pragma unroll
    for (int i = 0; i < 2; i++)
        #pragma unroll
        for (int j = 0; j < 8; j++)
            #pragma unroll
            for (int q = 0; q < 4; q++) acc[i][j][q] = 0.f;

    const int nch = K >> 5;
    for (int c = 0; c < nch; c++) {
        const int k0g = c * 32;
        __syncthreads();
        // ---- Stage A: 128m x 32k fp32 -> bf16 hi/lo (coalesced float4) ----
        #pragma unroll
        for (int q = 0; q < 4; q++) {
            int f  = tid + q * 256;
            int m  = f >> 3;
            int kq = (f & 7) * 4;
            float4 v = *(const float4*)&src[(size_t)(m0 + m) * K + k0g + kq];
            float xs[4] = {v.x, v.y, v.z, v.w};
            __nv_bfloat16 h[4], l[4];
            #pragma unroll
            for (int j = 0; j < 4; j++) {
                h[j] = __float2bfloat16_rn(xs[j]);
                l[j] = __float2bfloat16_rn(xs[j] - __bfloat162float(h[j]));
            }
            uint2 uh; uh.x = pb2(h[0], h[1]); uh.y = pb2(h[2], h[3]);
            uint2 ul; ul.x = pb2(l[0], l[1]); ul.y = pb2(l[2], l[3]);
            *(uint2*)&Ahi[m * 40 + kq] = uh;
            *(uint2*)&Alo[m * 40 + kq] = ul;
        }
        // ---- Stage B: 32k x 128n fp32 -> bf16 hi/lo (coalesced float4) ----
        #pragma unroll
        for (int q = 0; q < 4; q++) {
            int f  = tid + q * 256;
            int k  = f >> 5;
            int nq = (f & 31) * 4;
            float4 v = *(const float4*)&W[(size_t)(k0g + k) * 512 + n0 + nq];
            float xs[4] = {v.x, v.y, v.z, v.w};
            __nv_bfloat16 h[4], l[4];
            #pragma unroll
            for (int j = 0; j < 4; j++) {
                h[j] = __float2bfloat16_rn(xs[j]);
                l[j] = __float2bfloat16_rn(xs[j] - __bfloat162float(h[j]));
            }
            uint2 uh; uh.x = pb2(h[0], h[1]); uh.y = pb2(h[2], h[3]);
            uint2 ul; ul.x = pb2(l[0], l[1]); ul.y = pb2(l[2], l[3]);
            *(uint2*)&Bhi[k * 136 + nq] = uh;
            *(uint2*)&Blo[k * 136 + nq] = ul;
        }
        __syncthreads();

        // ---- Compute: 2 k-steps of m16n8k16 ----
        #pragma unroll
        for (int ks = 0; ks < 2; ks++) {
            const int k0 = ks * 16;
            uint32_t ah[2][4], al[2][4];
            #pragma unroll
            for (int mi = 0; mi < 2; mi++) {
                int row = wm * 32 + mi * 16 + (lane & 7) + ((lane >> 3) & 1) * 8;
                int col = k0 + (lane >> 4) * 8;
                uint32_t off = (uint32_t)(row * 40 + col) * 2;
                ldsm_x4(ah[mi], aHiB + off);
                ldsm_x4(al[mi], aLoB + off);
            }
            #pragma unroll
            for (int nc = 0; nc < 4; nc++) {
                int krow = k0 + (lane & 7) + ((lane >> 3) & 1) * 8;
                int ncol = wn * 64 + nc * 16 + (lane >> 4) * 8;
                uint32_t off = (uint32_t)(krow * 136 + ncol) * 2;
                uint32_t bh[4], bl[4];
                ldsm_x4_t(bh, bHiB + off);
                ldsm_x4_t(bl, bLoB + off);
                #pragma unroll
                for (int mi = 0; mi < 2; mi++) {
                    mma_bf16(acc[mi][nc*2+0], ah[mi], bh);
                    mma_bf16(acc[mi][nc*2+0], al[mi], bh);
                    mma_bf16(acc[mi][nc*2+0], ah[mi], bl);
                    mma_bf16(acc[mi][nc*2+1], ah[mi], bh + 2);
                    mma_bf16(acc[mi][nc*2+1], al[mi], bh + 2);
                    mma_bf16(acc[mi][nc*2+1], ah[mi], bl + 2);
                }
            }
        }
    }

    // ---- Epilogue: bias + tanh + store (float2 per fragment row) ----
    #pragma unroll
    for (int mi = 0; mi < 2; mi++) {
        #pragma unroll
        for (int ni = 0; ni < 8; ni++) {
            int m_g = m0 + wm * 32 + mi * 16 + (lane >> 2);
            int n_g = n0 + wn * 64 + ni * 8 + (lane & 3) * 2;
            float2 bv = *(const float2*)&bias[n_g];
            float2 o0, o1;
            o0.x = tanhf(acc[mi][ni][0] + bv.x);
            o0.y = tanhf(acc[mi][ni][1] + bv.y);
            o1.x = tanhf(acc[mi][ni][2] + bv.x);
            o1.y = tanhf(acc[mi][ni][3] + bv.y);
            *(float2*)&dst[(size_t)m_g * 512 + n_g] = o0;
            *(float2*)&dst[(size_t)(m_g + 8) * 512 + n_g] = o1;
        }
    }
}

// ---------------------------------------------------------------------------
// Barrier-free dual attention (R3 math; 128-thread blocks, d-tile 16,
// 256 blocks, 48KB smem -> multiple blocks/SM).
// gamma[b,s,t,d] = softmax_s( A[m,d]*H[n,d] + C[m,d]*F[n,d] ).
// tanh-bounded logits -> no max subtraction needed (exp2 range [0.13, 7.5]).
// ---------------------------------------------------------------------------
__global__ void __launch_bounds__(128)
attn_kernel(const float* __restrict__ H, const float* __restrict__ F,
            const float* __restrict__ Amat, const float* __restrict__ Cmat,
            const float* __restrict__ enc, const float* __restrict__ outp,
            float* __restrict__ concat, float* __restrict__ attn)
{
    extern __shared__ float sm[];
    float* Hs = sm;            // [256][16]
    float* Fs = sm + 4096;     // [256][16]
    float* Es = sm + 8192;     // [256][16]

    const int tid = threadIdx.x;
    const int dq  = (tid & 3) * 4;
    const int t   = tid >> 2;
    const int d0  = blockIdx.x * 16;
    const int b   = blockIdx.y;

    for (int idx = tid; idx < 1024; idx += 128) {
        int s  = idx >> 2;
        int dl = (idx & 3) << 2;
        size_t gidx = ((size_t)(b * Ss + s)) * Dd + d0 + dl;
        *(float4*)&Hs[s * 16 + dl] = *(const float4*)&H[gidx];
        *(float4*)&Fs[s * 16 + dl] = *(const float4*)&F[gidx];
        *(float4*)&Es[s * 16 + dl] = *(const float4*)&enc[gidx];
    }
    __syncthreads();

    const int m = b * Tt + t;
    const float L2E = 1.4426950408889634f;
    float4 a4 = *(const float4*)&Amat[(size_t)m * Dd + d0 + dq];
    float4 c4 = *(const float4*)&Cmat[(size_t)m * Dd + d0 + dq];
    a4.x *= L2E; a4.y *= L2E; a4.z *= L2E; a4.w *= L2E;
    c4.x *= L2E; c4.y *= L2E; c4.z *= L2E; c4.w *= L2E;

    float sx = 0.f, sy = 0.f, sz = 0.f, sw = 0.f;
    #pragma unroll 4
    for (int s = 0; s < Ss; s++) {
        float4 h = *(const float4*)&Hs[s * 16 + dq];
        float4 f = *(const float4*)&Fs[s * 16 + dq];
        sx += exp2f(fmaf(a4.x, h.x, c4.x * f.x));
        sy += exp2f(fmaf(a4.y, h.y, c4.y * f.y));
        sz += exp2f(fmaf(a4.z, h.z, c4.z * f.z));
        sw += exp2f(fmaf(a4.w, h.w, c4.w * f.w));
    }
    const float ix = 1.f / sx, iy = 1.f / sy, iz = 1.f / sz, iw = 1.f / sw;

    float cx = 0.f, cy = 0.f, cz = 0.f, cw = 0.f;
    float* ab = attn + (size_t)m * Ss * Dd + d0 + dq;
    #pragma unroll 2
    for (int s = 0; s < Ss; s++) {
        float4 h = *(const float4*)&Hs[s * 16 + dq];
        float4 f = *(const float4*)&Fs[s * 16 + dq];
        float4 e = *(const float4*)&Es[s * 16 + dq];
        float4 gv;
        gv.x = exp2f(fmaf(a4.x, h.x, c4.x * f.x)) * ix;
        gv.y = exp2f(fmaf(a4.y, h.y, c4.y * f.y)) * iy;
        gv.z = exp2f(fmaf(a4.z, h.z, c4.z * f.z)) * iz;
        gv.w = exp2f(fmaf(a4.w, h.w, c4.w * f.w)) * iw;
        *(float4*)&ab[(size_t)s * Dd] = gv;
        cx = fmaf(gv.x, e.x, cx);
        cy = fmaf(gv.y, e.y, cy);
        cz = fmaf(gv.z, e.z, cz);
        cw = fmaf(gv.w, e.w, cw);
    }

    float4 ct; ct.x = cx; ct.y = cy; ct.z = cz; ct.w = cw;
    *(float4*)&concat[(size_t)m * (2 * Dd) + Dd + d0 + dq] = ct;
    *(float4*)&concat[(size_t)m * (2 * Dd) + d0 + dq] =
        *(const float4*)&outp[(size_t)m * Dd + d0 + dq];
}

// ---------------------------------------------------------------------------
extern "C" void kernel_launch(void* const* d_in, const int* in_sizes, int n_in,
                              void* d_out, int out_size)
{
    const float* output = (const float*)d_in[0];   // [8,32,512]
    const float* enc    = (const float*)d_in[1];   // [256,8,512] flat [2048,512]
    const float* z      = (const float*)d_in[2];   // [8,256,128] flat [2048,128]
    const float* W1 = (const float*)d_in[3];
    const float* b1 = (const float*)d_in[4];
    const float* W2 = (const float*)d_in[5];
    const float* b2 = (const float*)d_in[6];
    const float* W3 = (const float*)d_in[7];
    const float* b3 = (const float*)d_in[8];
    const float* W4 = (const float*)d_in[9];
    const float* b4 = (const float*)d_in[10];

    float* concat = (float*)d_out;                       // [8,32,1024]
    float* attn   = concat + (size_t)Bb * Tt * 2 * Dd;   // [8,32,256,512]

    float *pH, *pF, *pA, *pC;
    cudaGetSymbolAddress((void**)&pH, g_H);
    cudaGetSymbolAddress((void**)&pF, g_F);
    cudaGetSymbolAddress((void**)&pA, g_A);
    cudaGetSymbolAddress((void**)&pC, g_C);

    megagemm_mma<<<144, 256>>>(enc, z, output,
                               W1, b1, W2, b2, W3, b3, W4, b4,
                               pH, pF, pA, pC);

    const int smem_attn = 3 * 4096 * (int)sizeof(float);  // 49152
    cudaFuncSetAttribute(attn_kernel, cudaFuncAttributeMaxDynamicSharedMemorySize, smem_attn);
    attn_kernel<<<dim3(32, Bb), 128, smem_attn>>>(pH, pF, pA, pC, enc, output, concat, attn);
}

// round 6
// speedup vs baseline: 4.2870x; 1.1645x over previous
#include <cuda_runtime.h>
#include <cuda_bf16.h>
#include <math.h>
#include <stdint.h>

#define Bb 8
#define Ss 256
#define Tt 32
#define Dd 512
#define NROWS 2048   // B*S
#define MROWS 256    // B*T

// Scratch (allocation-free rule: __device__ globals)
__device__ float g_H[NROWS * Dd];
__device__ float g_F[NROWS * Dd];
__device__ float g_A[MROWS * Dd];
__device__ float g_C[MROWS * Dd];

// ---------------------------------------------------------------------------
// Warp-MMA helpers (baseline PTX, compiles for plain sm_103)
// ---------------------------------------------------------------------------
__device__ __forceinline__ uint32_t smem_to_u32(const void* p) {
    uint32_t a;
    asm("{ .reg .u64 t; cvta.to.shared.u64 t, %1; cvt.u32.u64 %0, t; }"
        : "=r"(a) : "l"(p));
    return a;
}
__device__ __forceinline__ void ldsm_x4(uint32_t* r, uint32_t addr) {
    asm volatile("ldmatrix.sync.aligned.m8n8.x4.shared.b16 {%0,%1,%2,%3}, [%4];"
        : "=r"(r[0]), "=r"(r[1]), "=r"(r[2]), "=r"(r[3]) : "r"(addr));
}
__device__ __forceinline__ void ldsm_x4_t(uint32_t* r, uint32_t addr) {
    asm volatile("ldmatrix.sync.aligned.m8n8.x4.trans.shared.b16 {%0,%1,%2,%3}, [%4];"
        : "=r"(r[0]), "=r"(r[1]), "=r"(r[2]), "=r"(r[3]) : "r"(addr));
}
__device__ __forceinline__ void mma_bf16(float* d, const uint32_t* a, const uint32_t* b) {
    asm volatile("mma.sync.aligned.m16n8k16.row.col.f32.bf16.bf16.f32 "
        "{%0,%1,%2,%3}, {%4,%5,%6,%7}, {%8,%9}, {%0,%1,%2,%3};"
        : "+f"(d[0]), "+f"(d[1]), "+f"(d[2]), "+f"(d[3])
        : "r"(a[0]), "r"(a[1]), "r"(a[2]), "r"(a[3]), "r"(b[0]), "r"(b[1]));
}
__device__ __forceinline__ uint32_t pb2(__nv_bfloat16 a, __nv_bfloat16 b) {
    __nv_bfloat162 t; t.x = a; t.y = b;
    return *(uint32_t*)&t;
}

// ---------------------------------------------------------------------------
// Mega-GEMM via mma.sync bf16 with hi/lo split (3 MMAs / product term),
// software-pipelined: double-buffered smem, ONE barrier per chunk, next
// chunk's gmem loads prefetched into registers before the MMA burst.
// CTA: 128m x 128n, BK=32 fp32-k, 8 warps as 4m x 2n (warp 32x64).
// smem per buffer (bf16 elems): Ahi[128*40] Alo[128*40] Bhi[32*136] Blo[32*136]
// Blocks: [0,64) H (K=512) | [64,128) F (K=128) | [128,136) A | [136,144) C
// ---------------------------------------------------------------------------
#define A_ELE (128 * 40)
#define B_ELE (32 * 136)
#define BUF_ELE (2 * A_ELE + 2 * B_ELE)     // 18944 bf16 per buffer
#define GEMM_SMEM (2 * BUF_ELE * 2)         // 75776 bytes

__global__ void __launch_bounds__(256)
megagemm_mma(const float* __restrict__ enc, const float* __restrict__ z,
             const float* __restrict__ outp,
             const float* __restrict__ W1, const float* __restrict__ b1,
             const float* __restrict__ W2, const float* __restrict__ b2,
             const float* __restrict__ W3, const float* __restrict__ b3,
             const float* __restrict__ W4, const float* __restrict__ b4,
             float* __restrict__ H, float* __restrict__ F,
             float* __restrict__ A, float* __restrict__ C)
{
    extern __shared__ __nv_bfloat16 sbuf[];

    int bid = blockIdx.x;
    const float *src, *W, *bias;
    float* dst;
    int K;
    if (bid < 64)       { src = enc;  W = W1; bias = b1; dst = H; K = 512; }
    else if (bid < 128) { src = z;    W = W3; bias = b3; dst = F; K = 128; bid -= 64; }
    else if (bid < 136) { src = outp; W = W2; bias = b2; dst = A; K = 512; bid -= 128; }
    else                { src = outp; W = W4; bias = b4; dst = C; K = 512; bid -= 136; }
    const int nb = bid & 3;
    const int mb = bid >> 2;
    const int m0 = mb * 128, n0 = nb * 128;

    const int tid  = threadIdx.x;
    const int lane = tid & 31;
    const int wid  = tid >> 5;
    const int wm   = wid & 3;
    const int wn   = wid >> 2;

    // Per-thread staging coordinates (fixed across chunks)
    const int am  = tid >> 3;             // A row (two rows per 8 threads x4 q)
    const int akq = (tid & 7) * 4;        // A k-quad
    const int bk  = tid >> 5;             // B k-row base
    const int bnq = (tid & 31) * 4;       // B n-quad

    float acc[2][8][4];
    #pragma unroll
    for (int i = 0; i < 2; i++)
        #pragma unroll
        for (int j = 0; j < 8; j++)
            #pragma unroll
            for (int q = 0; q < 4; q++) acc[i][j][q] = 0.f;

    const int nch = K >> 5;
    float4 ra[4], rb[4];

    // Prologue: load chunk 0
    #pragma unroll
    for (int q = 0; q < 4; q++) {
        ra[q] = *(const float4*)&src[(size_t)(m0 + am + q * 32) * K + akq];
        rb[q] = *(const float4*)&W[(size_t)(bk + q * 8) * 512 + n0 + bnq];
    }

    for (int c = 0; c < nch; c++) {
        const int buf = c & 1;
        __nv_bfloat16* Ahi = sbuf + buf * BUF_ELE;
        __nv_bfloat16* Alo = Ahi + A_ELE;
        __nv_bfloat16* Bhi = Alo + A_ELE;
        __nv_bfloat16* Blo = Bhi + B_ELE;

        // Convert prefetched registers -> smem (hi/lo split)
        #pragma unroll
        for (int q = 0; q < 4; q++) {
            float xs[4] = {ra[q].x, ra[q].y, ra[q].z, ra[q].w};
            __nv_bfloat16 h[4], l[4];
            #pragma unroll
            for (int j = 0; j < 4; j++) {
                h[j] = __float2bfloat16_rn(xs[j]);
                l[j] = __float2bfloat16_rn(xs[j] - __bfloat162float(h[j]));
            }
            uint2 uh; uh.x = pb2(h[0], h[1]); uh.y = pb2(h[2], h[3]);
            uint2 ul; ul.x = pb2(l[0], l[1]); ul.y = pb2(l[2], l[3]);
            *(uint2*)&Ahi[(am + q * 32) * 40 + akq] = uh;
            *(uint2*)&Alo[(am + q * 32) * 40 + akq] = ul;
        }
        #pragma unroll
        for (int q = 0; q < 4; q++) {
            float xs[4] = {rb[q].x, rb[q].y, rb[q].z, rb[q].w};
            __nv_bfloat16 h[4], l[4];
            #pragma unroll
            for (int j = 0; j < 4; j++) {
                h[j] = __float2bfloat16_rn(xs[j]);
                l[j] = __float2bfloat16_rn(xs[j] - __bfloat162float(h[j]));
            }
            uint2 uh; uh.x = pb2(h[0], h[1]); uh.y = pb2(h[2], h[3]);
            uint2 ul; ul.x = pb2(l[0], l[1]); ul.y = pb2(l[2], l[3]);
            *(uint2*)&Bhi[(bk + q * 8) * 136 + bnq] = uh;
            *(uint2*)&Blo[(bk + q * 8) * 136 + bnq] = ul;
        }
        __syncthreads();

        // Prefetch next chunk while MMAs run
        if (c + 1 < nch) {
            const int k0g = (c + 1) * 32;
            #pragma unroll
            for (int q = 0; q < 4; q++) {
                ra[q] = *(const float4*)&src[(size_t)(m0 + am + q * 32) * K + k0g + akq];
                rb[q] = *(const float4*)&W[(size_t)(k0g + bk + q * 8) * 512 + n0 + bnq];
            }
        }

        const uint32_t aHiB = smem_to_u32(Ahi);
        const uint32_t aLoB = smem_to_u32(Alo);
        const uint32_t bHiB = smem_to_u32(Bhi);
        const uint32_t bLoB = smem_to_u32(Blo);

        #pragma unroll
        for (int ks = 0; ks < 2; ks++) {
            const int k0 = ks * 16;
            uint32_t ah[2][4], al[2][4];
            #pragma unroll
            for (int mi = 0; mi < 2; mi++) {
                int row = wm * 32 + mi * 16 + (lane & 15);
                int col = k0 + (lane >> 4) * 8;
                uint32_t off = (uint32_t)(row * 40 + col) * 2;
                ldsm_x4(ah[mi], aHiB + off);
                ldsm_x4(al[mi], aLoB + off);
            }
            #pragma unroll
            for (int nc = 0; nc < 4; nc++) {
                int krow = k0 + (lane & 15);
                int ncol = wn * 64 + nc * 16 + (lane >> 4) * 8;
                uint32_t off = (uint32_t)(krow * 136 + ncol) * 2;
                uint32_t bh[4], bl[4];
                ldsm_x4_t(bh, bHiB + off);
                ldsm_x4_t(bl, bLoB + off);
                #pragma unroll
                for (int mi = 0; mi < 2; mi++) {
                    mma_bf16(acc[mi][nc*2+0], ah[mi], bh);
                    mma_bf16(acc[mi][nc*2+0], al[mi], bh);
                    mma_bf16(acc[mi][nc*2+0], ah[mi], bl);
                    mma_bf16(acc[mi][nc*2+1], ah[mi], bh + 2);
                    mma_bf16(acc[mi][nc*2+1], al[mi], bh + 2);
                    mma_bf16(acc[mi][nc*2+1], ah[mi], bl + 2);
                }
            }
        }
    }

    // Epilogue: bias + tanh + store
    #pragma unroll
    for (int mi = 0; mi < 2; mi++) {
        #pragma unroll
        for (int ni = 0; ni < 8; ni++) {
            int m_g = m0 + wm * 32 + mi * 16 + (lane >> 2);
            int n_g = n0 + wn * 64 + ni * 8 + (lane & 3) * 2;
            float2 bv = *(const float2*)&bias[n_g];
            float2 o0, o1;
            o0.x = tanhf(acc[mi][ni][0] + bv.x);
            o0.y = tanhf(acc[mi][ni][1] + bv.y);
            o1.x = tanhf(acc[mi][ni][2] + bv.x);
            o1.y = tanhf(acc[mi][ni][3] + bv.y);
            *(float2*)&dst[(size_t)m_g * 512 + n_g] = o0;
            *(float2*)&dst[(size_t)(m_g + 8) * 512 + n_g] = o1;
        }
    }
}

// ---------------------------------------------------------------------------
// Barrier-free dual attention, high-occupancy variant.
// Block = (b, d-tile of 32), 1024 threads: thread = (t, single d).
// gamma[b,s,t,d] = softmax_s( A[m,d]*H[n,d] + C[m,d]*F[n,d] ); thread-local
// softmax (tanh-bounded logits -> no max subtraction). Warp = one t x 32
// consecutive d -> perfect 128B stores and conflict-free smem.
// Grid 128 blocks x 32 warps.
// ---------------------------------------------------------------------------
__global__ void __launch_bounds__(1024)
attn_kernel(const float* __restrict__ H, const float* __restrict__ F,
            const float* __restrict__ Amat, const float* __restrict__ Cmat,
            const float* __restrict__ enc, const float* __restrict__ outp,
            float* __restrict__ concat, float* __restrict__ attn)
{
    extern __shared__ float sm[];
    float* Hs = sm;            // [256][32]
    float* Fs = sm + 8192;     // [256][32]
    float* Es = sm + 16384;    // [256][32]

    const int tid = threadIdx.x;
    const int d   = tid & 31;
    const int t   = tid >> 5;
    const int d0  = blockIdx.x * 32;
    const int b   = blockIdx.y;

    // Load tiles: 8192 floats each = 2048 float4, 1024 threads -> 2 iters
    for (int idx = tid; idx < 2048; idx += 1024) {
        int s  = idx >> 3;
        int dl = (idx & 7) << 2;
        size_t g = ((size_t)(b * Ss + s)) * Dd + d0 + dl;
        *(float4*)&Hs[s * 32 + dl] = *(const float4*)&H[g];
        *(float4*)&Fs[s * 32 + dl] = *(const float4*)&F[g];
        *(float4*)&Es[s * 32 + dl] = *(const float4*)&enc[g];
    }
    __syncthreads();

    const int m = b * Tt + t;
    const float L2E = 1.4426950408889634f;
    const float a = Amat[(size_t)m * Dd + d0 + d] * L2E;
    const float c = Cmat[(size_t)m * Dd + d0 + d] * L2E;

    // Pass 1: softmax denominator (thread-local)
    float sum = 0.f;
    #pragma unroll 8
    for (int s = 0; s < Ss; s++)
        sum += exp2f(fmaf(a, Hs[s * 32 + d], c * Fs[s * 32 + d]));
    const float inv = 1.f / sum;

    // Pass 2: write gamma + accumulate context
    float ctx = 0.f;
    float* ab = attn + (size_t)m * Ss * Dd + d0 + d;
    #pragma unroll 4
    for (int s = 0; s < Ss; s++) {
        float g = exp2f(fmaf(a, Hs[s * 32 + d], c * Fs[s * 32 + d])) * inv;
        ab[(size_t)s * Dd] = g;
        ctx = fmaf(g, Es[s * 32 + d], ctx);
    }

    concat[(size_t)m * (2 * Dd) + Dd + d0 + d] = ctx;
    concat[(size_t)m * (2 * Dd) + d0 + d] = outp[(size_t)m * Dd + d0 + d];
}

// ---------------------------------------------------------------------------
extern "C" void kernel_launch(void* const* d_in, const int* in_sizes, int n_in,
                              void* d_out, int out_size)
{
    const float* output = (const float*)d_in[0];   // [8,32,512]
    const float* enc    = (const float*)d_in[1];   // [256,8,512] flat [2048,512]
    const float* z      = (const float*)d_in[2];   // [8,256,128] flat [2048,128]
    const float* W1 = (const float*)d_in[3];
    const float* b1 = (const float*)d_in[4];
    const float* W2 = (const float*)d_in[5];
    const float* b2 = (const float*)d_in[6];
    const float* W3 = (const float*)d_in[7];
    const float* b3 = (const float*)d_in[8];
    const float* W4 = (const float*)d_in[9];
    const float* b4 = (const float*)d_in[10];

    float* concat = (float*)d_out;                       // [8,32,1024]
    float* attn   = concat + (size_t)Bb * Tt * 2 * Dd;   // [8,32,256,512]

    float *pH, *pF, *pA, *pC;
    cudaGetSymbolAddress((void**)&pH, g_H);
    cudaGetSymbolAddress((void**)&pF, g_F);
    cudaGetSymbolAddress((void**)&pA, g_A);
    cudaGetSymbolAddress((void**)&pC, g_C);

    cudaFuncSetAttribute(megagemm_mma, cudaFuncAttributeMaxDynamicSharedMemorySize, GEMM_SMEM);
    megagemm_mma<<<144, 256, GEMM_SMEM>>>(enc, z, output,
                                          W1, b1, W2, b2, W3, b3, W4, b4,
                                          pH, pF, pA, pC);

    const int smem_attn = 3 * 8192 * (int)sizeof(float);  // 98304
    cudaFuncSetAttribute(attn_kernel, cudaFuncAttributeMaxDynamicSharedMemorySize, smem_attn);
    attn_kernel<<<dim3(16, Bb), 1024, smem_attn>>>(pH, pF, pA, pC, enc, output, concat, attn);
}